// round 2
// baseline (speedup 1.0000x reference)
#include <cuda_runtime.h>

#define NT 4096      // total tokens B*S
#define HD 1024      // hidden dim
#define ID 2048      // intermediate dim
#define NE 8         // experts
#define NP 8192      // NT * TOPK pairs

// Scratch (static device memory — allowed; no cudaMalloc anywhere)
__device__ int   d_cnt[NE];
__device__ int   d_list[NE][NP];
__device__ __align__(16) float d_h[(size_t)NP * ID];   // 64 MB intermediate h

__device__ __forceinline__ float silu_f(float v) {
    return v / (1.0f + __expf(-v));
}

// ---------------------------------------------------------------------------
// Kernel 0: zero output + routing counters
// ---------------------------------------------------------------------------
__global__ void k_zero(float* __restrict__ out) {
    const int stride = gridDim.x * blockDim.x;
    int i = blockIdx.x * blockDim.x + threadIdx.x;
    float4 z = make_float4(0.f, 0.f, 0.f, 0.f);
    float4* o4 = reinterpret_cast<float4*>(out);
    const int n4 = (NT * HD) / 4;
    for (int j = i; j < n4; j += stride) o4[j] = z;
    if (blockIdx.x == 0 && threadIdx.x < NE) d_cnt[threadIdx.x] = 0;
}

// ---------------------------------------------------------------------------
// Kernel 1: route (token,slot) pairs into per-expert lists
// NOTE: expert_indices is int32 on device (JAX default x64-disabled demotes
// jnp.int64 requests to int32).
// ---------------------------------------------------------------------------
__global__ void k_route(const int* __restrict__ eidx) {
    int p = blockIdx.x * blockDim.x + threadIdx.x;
    if (p < NP) {
        int e = eidx[p];
        if (e >= 0 && e < NE) {               // defensive clamp
            int pos = atomicAdd(&d_cnt[e], 1);
            d_list[e][pos] = p;
        }
    }
}

// Map a global m-tile index to (expert, local m-tile).
__device__ __forceinline__ bool map_tile(int g, int* pe, int* pmt) {
    int e = -1, mt = 0;
#pragma unroll
    for (int ee = 0; ee < NE; ee++) {
        int nt = (d_cnt[ee] + 63) >> 6;
        if (e < 0) {
            if (g < nt) { e = ee; mt = g; }
            else g -= nt;
        }
    }
    *pe = e; *pmt = mt;
    return e >= 0;
}

// ---------------------------------------------------------------------------
// Kernel 2: gathered gate/up GEMM + silu*up, writes d_h
//   C[64 rows, 64 i-cols] per block; K = HD
// ---------------------------------------------------------------------------
__global__ void __launch_bounds__(256, 2)
k_gateup(const float* __restrict__ x,
         const float* __restrict__ gw,
         const float* __restrict__ uw) {
    int e, mt;
    if (!map_tile(blockIdx.y, &e, &mt)) return;
    const int n_e   = d_cnt[e];
    const int m0    = mt * 64;
    const int mrows = min(64, n_e - m0);
    const int i0    = blockIdx.x * 64;

    __shared__ __align__(16) float As[16][68];
    __shared__ __align__(16) float Bg[16][68];
    __shared__ __align__(16) float Bu[16][68];

    const int tid = threadIdx.x;
    const int tx  = tid & 15;      // compute col group
    const int ty  = tid >> 4;      // compute row group
    const int kk  = tid & 15;      // load: k within tile
    const int lr  = tid >> 4;      // load: row base

    const float* aptr[4];
    bool         aval[4];
    const float* gptr[4];
    const float* uptr[4];
#pragma unroll
    for (int it = 0; it < 4; it++) {
        int r = lr + it * 16;
        bool v = r < mrows;
        int p = v ? d_list[e][m0 + r] : 0;
        int t = p >> 1;
        aptr[it] = x + (size_t)t * HD + kk;
        aval[it] = v;
        int n = lr + it * 16;
        gptr[it] = gw + ((size_t)e * ID + i0 + n) * HD + kk;
        uptr[it] = uw + ((size_t)e * ID + i0 + n) * HD + kk;
    }

    float cg[4][4] = {};
    float cu[4][4] = {};

    for (int k0 = 0; k0 < HD; k0 += 16) {
#pragma unroll
        for (int it = 0; it < 4; it++) {
            int r = lr + it * 16;
            As[kk][r] = aval[it] ? __ldg(aptr[it] + k0) : 0.0f;
            Bg[kk][r] = __ldg(gptr[it] + k0);
            Bu[kk][r] = __ldg(uptr[it] + k0);
        }
        __syncthreads();
#pragma unroll
        for (int k = 0; k < 16; k++) {
            float4 a  = *(const float4*)&As[k][ty * 4];
            float4 bg = *(const float4*)&Bg[k][tx * 4];
            float4 bu = *(const float4*)&Bu[k][tx * 4];
            float am[4]  = {a.x, a.y, a.z, a.w};
            float bgm[4] = {bg.x, bg.y, bg.z, bg.w};
            float bum[4] = {bu.x, bu.y, bu.z, bu.w};
#pragma unroll
            for (int mm = 0; mm < 4; mm++)
#pragma unroll
                for (int nn = 0; nn < 4; nn++) {
                    cg[mm][nn] = fmaf(am[mm], bgm[nn], cg[mm][nn]);
                    cu[mm][nn] = fmaf(am[mm], bum[nn], cu[mm][nn]);
                }
        }
        __syncthreads();
    }

#pragma unroll
    for (int mm = 0; mm < 4; mm++) {
        int m = ty * 4 + mm;
        if (m < mrows) {
            int p = d_list[e][m0 + m];
            float4 hv;
            hv.x = silu_f(cg[mm][0]) * cu[mm][0];
            hv.y = silu_f(cg[mm][1]) * cu[mm][1];
            hv.z = silu_f(cg[mm][2]) * cu[mm][2];
            hv.w = silu_f(cg[mm][3]) * cu[mm][3];
            *(float4*)&d_h[(size_t)p * ID + i0 + tx * 4] = hv;
        }
    }
}

// ---------------------------------------------------------------------------
// Kernel 3: gathered down GEMM, weighted atomic scatter into out
//   C[64 rows, 64 h-cols] per block; K = ID
// ---------------------------------------------------------------------------
__global__ void __launch_bounds__(256, 2)
k_down(const float* __restrict__ ew,
       const float* __restrict__ dw,
       float* __restrict__ out) {
    int e, mt;
    if (!map_tile(blockIdx.y, &e, &mt)) return;
    const int n_e   = d_cnt[e];
    const int m0    = mt * 64;
    const int mrows = min(64, n_e - m0);
    const int n0    = blockIdx.x * 64;

    __shared__ __align__(16) float As[16][68];
    __shared__ __align__(16) float Bd[16][68];

    const int tid = threadIdx.x;
    const int tx  = tid & 15;
    const int ty  = tid >> 4;
    const int kk  = tid & 15;
    const int lr  = tid >> 4;

    const float* aptr[4];
    bool         aval[4];
    const float* bptr[4];
#pragma unroll
    for (int it = 0; it < 4; it++) {
        int r = lr + it * 16;
        bool v = r < mrows;
        int p = v ? d_list[e][m0 + r] : 0;
        aptr[it] = d_h + (size_t)p * ID + kk;
        aval[it] = v;
        int n = lr + it * 16;
        bptr[it] = dw + ((size_t)e * HD + n0 + n) * ID + kk;
    }

    float c[4][4] = {};

    for (int k0 = 0; k0 < ID; k0 += 16) {
#pragma unroll
        for (int it = 0; it < 4; it++) {
            int r = lr + it * 16;
            As[kk][r] = aval[it] ? aptr[it][k0] : 0.0f;
            Bd[kk][r] = __ldg(bptr[it] + k0);
        }
        __syncthreads();
#pragma unroll
        for (int k = 0; k < 16; k++) {
            float4 a = *(const float4*)&As[k][ty * 4];
            float4 b = *(const float4*)&Bd[k][tx * 4];
            float am[4] = {a.x, a.y, a.z, a.w};
            float bm[4] = {b.x, b.y, b.z, b.w};
#pragma unroll
            for (int mm = 0; mm < 4; mm++)
#pragma unroll
                for (int nn = 0; nn < 4; nn++)
                    c[mm][nn] = fmaf(am[mm], bm[nn], c[mm][nn]);
        }
        __syncthreads();
    }

#pragma unroll
    for (int mm = 0; mm < 4; mm++) {
        int m = ty * 4 + mm;
        if (m < mrows) {
            int p = d_list[e][m0 + m];
            int t = p >> 1;
            float w = __ldg(&ew[p]);
            float* obase = out + (size_t)t * HD + n0 + tx * 4;
#pragma unroll
            for (int nn = 0; nn < 4; nn++)
                atomicAdd(obase + nn, w * c[mm][nn]);
        }
    }
}

// ---------------------------------------------------------------------------
// Launch
// ---------------------------------------------------------------------------
extern "C" void kernel_launch(void* const* d_in, const int* in_sizes, int n_in,
                              void* d_out, int out_size) {
    const float* x    = (const float*)d_in[0];
    const int*   eidx = (const int*)d_in[1];   // int32 (JAX x64 disabled)
    const float* ew   = (const float*)d_in[2];
    const float* gw   = (const float*)d_in[3];
    const float* uw   = (const float*)d_in[4];
    const float* dw   = (const float*)d_in[5];
    float*       out  = (float*)d_out;

    k_zero<<<1024, 256>>>(out);
    k_route<<<NP / 256, 256>>>(eidx);

    // max Σ_e ceil(cnt_e/64) = 8192/64 + (NE-1) = 135 -> 136 is safe
    dim3 g1(ID / 64, 136);
    k_gateup<<<g1, 256>>>(x, gw, uw);

    dim3 g2(HD / 64, 136);
    k_down<<<g2, 256>>>(ew, dw, out);
}

// round 3
// speedup vs baseline: 2.3448x; 2.3448x over previous
#include <cuda_runtime.h>
#include <cuda_bf16.h>
#include <cstdint>

#define NT 4096      // tokens B*S
#define HD 1024      // hidden dim
#define ID 2048      // intermediate dim
#define NE 8         // experts
#define NP 8192      // NT * TOPK

#define SKP   40     // padded bf16 row stride in smem (32 k + 8 pad)
#define KCH   32     // K chunk

// ---------------- static device scratch (no cudaMalloc) ----------------
__device__ int d_cnt[NE];
__device__ int d_list[NE][NP];

__device__ __align__(16) __nv_bfloat16 d_xhi[(size_t)NT * HD];
__device__ __align__(16) __nv_bfloat16 d_xlo[(size_t)NT * HD];
__device__ __align__(16) __nv_bfloat16 d_ghi[(size_t)NE * ID * HD];
__device__ __align__(16) __nv_bfloat16 d_glo[(size_t)NE * ID * HD];
__device__ __align__(16) __nv_bfloat16 d_uhi[(size_t)NE * ID * HD];
__device__ __align__(16) __nv_bfloat16 d_ulo[(size_t)NE * ID * HD];
__device__ __align__(16) __nv_bfloat16 d_dhi[(size_t)NE * HD * ID];
__device__ __align__(16) __nv_bfloat16 d_dlo[(size_t)NE * HD * ID];
__device__ __align__(16) __nv_bfloat16 d_hhi[(size_t)NP * ID];
__device__ __align__(16) __nv_bfloat16 d_hlo[(size_t)NP * ID];

// ---------------- PTX helpers ----------------
__device__ __forceinline__ uint32_t smem_u32(const void* p) {
    return (uint32_t)__cvta_generic_to_shared(p);
}
__device__ __forceinline__ void cp16(uint32_t dst, const void* src) {
    asm volatile("cp.async.cg.shared.global [%0], [%1], 16;\n" :: "r"(dst), "l"(src));
}
__device__ __forceinline__ void cp_commit() {
    asm volatile("cp.async.commit_group;\n");
}
template <int N>
__device__ __forceinline__ void cp_wait() {
    asm volatile("cp.async.wait_group %0;\n" :: "n"(N));
}
__device__ __forceinline__ void ldsm4(uint32_t r[4], uint32_t addr) {
    asm volatile("ldmatrix.sync.aligned.m8n8.x4.shared.b16 {%0,%1,%2,%3}, [%4];"
                 : "=r"(r[0]), "=r"(r[1]), "=r"(r[2]), "=r"(r[3]) : "r"(addr));
}
__device__ __forceinline__ void ldsm2(uint32_t r[2], uint32_t addr) {
    asm volatile("ldmatrix.sync.aligned.m8n8.x2.shared.b16 {%0,%1}, [%2];"
                 : "=r"(r[0]), "=r"(r[1]) : "r"(addr));
}
__device__ __forceinline__ void mma_bf16(float c[4], const uint32_t a[4], const uint32_t b[2]) {
    asm volatile(
        "mma.sync.aligned.m16n8k16.row.col.f32.bf16.bf16.f32 "
        "{%0,%1,%2,%3}, {%4,%5,%6,%7}, {%8,%9}, {%0,%1,%2,%3};"
        : "+f"(c[0]), "+f"(c[1]), "+f"(c[2]), "+f"(c[3])
        : "r"(a[0]), "r"(a[1]), "r"(a[2]), "r"(a[3]), "r"(b[0]), "r"(b[1]));
}
__device__ __forceinline__ float silu_f(float v) { return v / (1.0f + __expf(-v)); }

__device__ __forceinline__ uint32_t pack_bf2(float a, float b) {
    __nv_bfloat162 t;
    t.x = __float2bfloat16_rn(a);
    t.y = __float2bfloat16_rn(b);
    return *reinterpret_cast<uint32_t*>(&t);
}

// ---------------- kernel 0: zero out + counters ----------------
__global__ void k_zero(float* __restrict__ out) {
    const int stride = gridDim.x * blockDim.x;
    int i = blockIdx.x * blockDim.x + threadIdx.x;
    float4 z = make_float4(0.f, 0.f, 0.f, 0.f);
    float4* o4 = reinterpret_cast<float4*>(out);
    const int n4 = (NT * HD) / 4;
    for (int j = i; j < n4; j += stride) o4[j] = z;
    if (blockIdx.x == 0 && threadIdx.x < NE) d_cnt[threadIdx.x] = 0;
}

// ---------------- kernel 1: routing (expert_indices is int32) ----------------
__global__ void k_route(const int* __restrict__ eidx) {
    int p = blockIdx.x * blockDim.x + threadIdx.x;
    if (p < NP) {
        int e = eidx[p];
        if (e >= 0 && e < NE) {
            int pos = atomicAdd(&d_cnt[e], 1);
            d_list[e][pos] = p;
        }
    }
}

// ---------------- kernel: fp32 -> bf16 hi/lo split ----------------
__global__ void k_split(const float* __restrict__ s,
                        __nv_bfloat16* __restrict__ hi,
                        __nv_bfloat16* __restrict__ lo, int n4) {
    int i = blockIdx.x * blockDim.x + threadIdx.x;
    int stride = gridDim.x * blockDim.x;
    const float4* s4 = (const float4*)s;
    uint2* h2 = (uint2*)hi;
    uint2* l2 = (uint2*)lo;
    for (int j = i; j < n4; j += stride) {
        float4 v = s4[j];
        __nv_bfloat16 h0 = __float2bfloat16_rn(v.x);
        __nv_bfloat16 h1 = __float2bfloat16_rn(v.y);
        __nv_bfloat16 h2v = __float2bfloat16_rn(v.z);
        __nv_bfloat16 h3 = __float2bfloat16_rn(v.w);
        float l0 = v.x - __bfloat162float(h0);
        float l1 = v.y - __bfloat162float(h1);
        float l2v = v.z - __bfloat162float(h2v);
        float l3 = v.w - __bfloat162float(h3);
        uint2 H, L;
        __nv_bfloat162 t;
        t.x = h0; t.y = h1; H.x = *reinterpret_cast<uint32_t*>(&t);
        t.x = h2v; t.y = h3; H.y = *reinterpret_cast<uint32_t*>(&t);
        L.x = pack_bf2(l0, l1);
        L.y = pack_bf2(l2v, l3);
        h2[j] = H;
        l2[j] = L;
    }
}

// Map global m-tile (128 rows) to (expert, local tile).
__device__ __forceinline__ bool map_tile(int g, int* pe, int* pmt) {
    int e = -1, mt = 0;
#pragma unroll
    for (int ee = 0; ee < NE; ee++) {
        int nt = (d_cnt[ee] + 127) >> 7;
        if (e < 0) {
            if (g < nt) { e = ee; mt = g; }
            else g -= nt;
        }
    }
    *pe = e; *pmt = mt;
    return e >= 0;
}

// ======================================================================
// Kernel 2: gate/up GEMM (M=128 rows, N=64 i-cols, K=HD) split-bf16 MMA
// smem buffer layout (bytes): Ahi 0..10240, Alo 10240.., Bg_hi 20480,
// Bg_lo 25600, Bu_hi 30720, Bu_lo 35840; buffer stride 40960, 2 buffers.
// ======================================================================
#define GU_BUF 40960
#define GU_ALO 10240
#define GU_BGH 20480
#define GU_BGL 25600
#define GU_BUH 30720
#define GU_BUL 35840

__global__ void __launch_bounds__(256)
k_gateup() {
    int e, mt;
    if (!map_tile(blockIdx.y, &e, &mt)) return;
    const int n_e = d_cnt[e];
    const int m0  = mt * 128;
    const int i0  = blockIdx.x * 64;

    extern __shared__ __align__(16) unsigned char smem[];
    const uint32_t sbase = smem_u32(smem);

    const int tid  = threadIdx.x;
    const int wid  = tid >> 5;
    const int lane = tid & 31;

    // ---- staging pointers (element units; +kc at issue) ----
    const int sr = tid >> 2;      // 0..63
    const int sc = tid & 3;       // 16B unit -> 8 bf16
    const __nv_bfloat16 *axh[2], *axl[2];
#pragma unroll
    for (int rp = 0; rp < 2; rp++) {
        int r = sr + rp * 64;
        int p = (m0 + r < n_e) ? d_list[e][m0 + r] : d_list[e][m0];
        size_t t = (size_t)(p >> 1);
        axh[rp] = d_xhi + t * HD + sc * 8;
        axl[rp] = d_xlo + t * HD + sc * 8;
    }
    const size_t wb = ((size_t)e * ID + i0 + sr) * HD + sc * 8;
    const __nv_bfloat16* gh = d_ghi + wb;
    const __nv_bfloat16* gl = d_glo + wb;
    const __nv_bfloat16* uh = d_uhi + wb;
    const __nv_bfloat16* ul = d_ulo + wb;

    const uint32_t adst = (uint32_t)(sr * (SKP * 2) + sc * 16);
    const uint32_t bdst = (uint32_t)(sr * (SKP * 2) + sc * 16);

    // ---- fragment addresses (relative, lane-dependent) ----
    const int wm0 = (wid >> 1) * 32;
    const int wn0 = (wid & 1) * 32;
    const int lrA = lane & 15, lcA = lane >> 4;
    uint32_t aoff[2];
#pragma unroll
    for (int fm = 0; fm < 2; fm++)
        aoff[fm] = (uint32_t)(((wm0 + fm * 16 + lrA) * SKP + lcA * 8) * 2);
    const int lB = lane & 15;
    uint32_t boff[4];
#pragma unroll
    for (int fn = 0; fn < 4; fn++)
        boff[fn] = (uint32_t)(((wn0 + fn * 8 + (lB & 7)) * SKP + (lB >> 3) * 8) * 2);

    float cg[2][4][4] = {};
    float cu[2][4][4] = {};

    auto stage = [&](int kc, int b) {
        uint32_t B0 = sbase + (uint32_t)b * GU_BUF;
#pragma unroll
        for (int rp = 0; rp < 2; rp++) {
            uint32_t d = B0 + adst + (uint32_t)rp * 64 * (SKP * 2);
            cp16(d, axh[rp] + kc);
            cp16(d + GU_ALO, axl[rp] + kc);
        }
        uint32_t d = B0 + GU_BGH + bdst;
        cp16(d, gh + kc);
        cp16(d + (GU_BGL - GU_BGH), gl + kc);
        cp16(d + (GU_BUH - GU_BGH), uh + kc);
        cp16(d + (GU_BUL - GU_BGH), ul + kc);
    };

    stage(0, 0);
    cp_commit();

    const int nch = HD / KCH;   // 32
    for (int ic = 0; ic < nch; ic++) {
        if (ic + 1 < nch) {
            stage((ic + 1) * KCH, (ic + 1) & 1);
            cp_commit();
            cp_wait<1>();
        } else {
            cp_wait<0>();
        }
        __syncthreads();
        const uint32_t B0 = sbase + (uint32_t)(ic & 1) * GU_BUF;
#pragma unroll
        for (int ks = 0; ks < KCH; ks += 16) {
            uint32_t ah[2][4], al[2][4];
#pragma unroll
            for (int fm = 0; fm < 2; fm++) {
                ldsm4(ah[fm], B0 + aoff[fm] + ks * 2);
                ldsm4(al[fm], B0 + GU_ALO + aoff[fm] + ks * 2);
            }
            uint32_t bgh[4][2], bgl[4][2], buh[4][2], bul[4][2];
#pragma unroll
            for (int fn = 0; fn < 4; fn++) {
                ldsm2(bgh[fn], B0 + GU_BGH + boff[fn] + ks * 2);
                ldsm2(bgl[fn], B0 + GU_BGL + boff[fn] + ks * 2);
                ldsm2(buh[fn], B0 + GU_BUH + boff[fn] + ks * 2);
                ldsm2(bul[fn], B0 + GU_BUL + boff[fn] + ks * 2);
            }
#pragma unroll
            for (int fm = 0; fm < 2; fm++)
#pragma unroll
                for (int fn = 0; fn < 4; fn++) {
                    mma_bf16(cg[fm][fn], ah[fm], bgh[fn]);
                    mma_bf16(cu[fm][fn], ah[fm], buh[fn]);
                    mma_bf16(cg[fm][fn], ah[fm], bgl[fn]);
                    mma_bf16(cu[fm][fn], ah[fm], bul[fn]);
                    mma_bf16(cg[fm][fn], al[fm], bgh[fn]);
                    mma_bf16(cu[fm][fn], al[fm], buh[fn]);
                }
        }
        __syncthreads();
    }

    // ---- epilogue: h = silu(gate)*up, split to hi/lo planes ----
    const int g4  = lane >> 2;
    const int tig = lane & 3;
#pragma unroll
    for (int fm = 0; fm < 2; fm++) {
#pragma unroll
        for (int fn = 0; fn < 4; fn++) {
            int cc = wn0 + fn * 8 + tig * 2;
            int r0 = wm0 + fm * 16 + g4;
            int r1 = r0 + 8;
            float v00 = silu_f(cg[fm][fn][0]) * cu[fm][fn][0];
            float v01 = silu_f(cg[fm][fn][1]) * cu[fm][fn][1];
            float v10 = silu_f(cg[fm][fn][2]) * cu[fm][fn][2];
            float v11 = silu_f(cg[fm][fn][3]) * cu[fm][fn][3];
            if (m0 + r0 < n_e) {
                int p = d_list[e][m0 + r0];
                size_t idx = (size_t)p * ID + i0 + cc;
                __nv_bfloat16 h0 = __float2bfloat16_rn(v00);
                __nv_bfloat16 h1 = __float2bfloat16_rn(v01);
                __nv_bfloat162 H; H.x = h0; H.y = h1;
                *reinterpret_cast<uint32_t*>(&d_hhi[idx]) = *reinterpret_cast<uint32_t*>(&H);
                *reinterpret_cast<uint32_t*>(&d_hlo[idx]) =
                    pack_bf2(v00 - __bfloat162float(h0), v01 - __bfloat162float(h1));
            }
            if (m0 + r1 < n_e) {
                int p = d_list[e][m0 + r1];
                size_t idx = (size_t)p * ID + i0 + cc;
                __nv_bfloat16 h0 = __float2bfloat16_rn(v10);
                __nv_bfloat16 h1 = __float2bfloat16_rn(v11);
                __nv_bfloat162 H; H.x = h0; H.y = h1;
                *reinterpret_cast<uint32_t*>(&d_hhi[idx]) = *reinterpret_cast<uint32_t*>(&H);
                *reinterpret_cast<uint32_t*>(&d_hlo[idx]) =
                    pack_bf2(v10 - __bfloat162float(h0), v11 - __bfloat162float(h1));
            }
        }
    }
}

// ======================================================================
// Kernel 3: down GEMM (M=128 rows, N=64 h-cols, K=ID) split-bf16 MMA
// buffer: Ahi 0, Alo 10240, Bhi 20480, Blo 25600; stride 30720, 2 bufs.
// ======================================================================
#define DN_BUF 30720
#define DN_ALO 10240
#define DN_BH  20480
#define DN_BL  25600

__global__ void __launch_bounds__(256)
k_down(const float* __restrict__ ew, float* __restrict__ out) {
    int e, mt;
    if (!map_tile(blockIdx.y, &e, &mt)) return;
    const int n_e = d_cnt[e];
    const int m0  = mt * 128;
    const int n0  = blockIdx.x * 64;

    extern __shared__ __align__(16) unsigned char smem[];
    const uint32_t sbase = smem_u32(smem);

    const int tid  = threadIdx.x;
    const int wid  = tid >> 5;
    const int lane = tid & 31;

    const int sr = tid >> 2;
    const int sc = tid & 3;
    const __nv_bfloat16 *ahp[2], *alp[2];
#pragma unroll
    for (int rp = 0; rp < 2; rp++) {
        int r = sr + rp * 64;
        int p = (m0 + r < n_e) ? d_list[e][m0 + r] : d_list[e][m0];
        ahp[rp] = d_hhi + (size_t)p * ID + sc * 8;
        alp[rp] = d_hlo + (size_t)p * ID + sc * 8;
    }
    const size_t wb = ((size_t)e * HD + n0 + sr) * ID + sc * 8;
    const __nv_bfloat16* bh = d_dhi + wb;
    const __nv_bfloat16* bl = d_dlo + wb;

    const uint32_t adst = (uint32_t)(sr * (SKP * 2) + sc * 16);

    const int wm0 = (wid >> 1) * 32;
    const int wn0 = (wid & 1) * 32;
    const int lrA = lane & 15, lcA = lane >> 4;
    uint32_t aoff[2];
#pragma unroll
    for (int fm = 0; fm < 2; fm++)
        aoff[fm] = (uint32_t)(((wm0 + fm * 16 + lrA) * SKP + lcA * 8) * 2);
    const int lB = lane & 15;
    uint32_t boff[4];
#pragma unroll
    for (int fn = 0; fn < 4; fn++)
        boff[fn] = (uint32_t)(((wn0 + fn * 8 + (lB & 7)) * SKP + (lB >> 3) * 8) * 2);

    float c[2][4][4] = {};

    auto stage = [&](int kc, int b) {
        uint32_t B0 = sbase + (uint32_t)b * DN_BUF;
#pragma unroll
        for (int rp = 0; rp < 2; rp++) {
            uint32_t d = B0 + adst + (uint32_t)rp * 64 * (SKP * 2);
            cp16(d, ahp[rp] + kc);
            cp16(d + DN_ALO, alp[rp] + kc);
        }
        uint32_t d = B0 + DN_BH + adst;
        cp16(d, bh + kc);
        cp16(d + (DN_BL - DN_BH), bl + kc);
    };

    stage(0, 0);
    cp_commit();

    const int nch = ID / KCH;   // 64
    for (int ic = 0; ic < nch; ic++) {
        if (ic + 1 < nch) {
            stage((ic + 1) * KCH, (ic + 1) & 1);
            cp_commit();
            cp_wait<1>();
        } else {
            cp_wait<0>();
        }
        __syncthreads();
        const uint32_t B0 = sbase + (uint32_t)(ic & 1) * DN_BUF;
#pragma unroll
        for (int ks = 0; ks < KCH; ks += 16) {
            uint32_t ah[2][4], al[2][4];
#pragma unroll
            for (int fm = 0; fm < 2; fm++) {
                ldsm4(ah[fm], B0 + aoff[fm] + ks * 2);
                ldsm4(al[fm], B0 + DN_ALO + aoff[fm] + ks * 2);
            }
            uint32_t bhf[4][2], blf[4][2];
#pragma unroll
            for (int fn = 0; fn < 4; fn++) {
                ldsm2(bhf[fn], B0 + DN_BH + boff[fn] + ks * 2);
                ldsm2(blf[fn], B0 + DN_BL + boff[fn] + ks * 2);
            }
#pragma unroll
            for (int fm = 0; fm < 2; fm++)
#pragma unroll
                for (int fn = 0; fn < 4; fn++) {
                    mma_bf16(c[fm][fn], ah[fm], bhf[fn]);
                    mma_bf16(c[fm][fn], ah[fm], blf[fn]);
                    mma_bf16(c[fm][fn], al[fm], bhf[fn]);
                }
        }
        __syncthreads();
    }

    // ---- epilogue: weighted atomic scatter ----
    const int g4  = lane >> 2;
    const int tig = lane & 3;
#pragma unroll
    for (int fm = 0; fm < 2; fm++) {
        int r0 = wm0 + fm * 16 + g4;
        int r1 = r0 + 8;
        bool v0 = (m0 + r0 < n_e), v1 = (m0 + r1 < n_e);
        int p0 = v0 ? d_list[e][m0 + r0] : 0;
        int p1 = v1 ? d_list[e][m0 + r1] : 0;
        float w0 = v0 ? __ldg(&ew[p0]) : 0.0f;
        float w1 = v1 ? __ldg(&ew[p1]) : 0.0f;
        float* ob0 = out + (size_t)(p0 >> 1) * HD + n0;
        float* ob1 = out + (size_t)(p1 >> 1) * HD + n0;
#pragma unroll
        for (int fn = 0; fn < 4; fn++) {
            int cc = wn0 + fn * 8 + tig * 2;
            if (v0) {
                atomicAdd(ob0 + cc,     w0 * c[fm][fn][0]);
                atomicAdd(ob0 + cc + 1, w0 * c[fm][fn][1]);
            }
            if (v1) {
                atomicAdd(ob1 + cc,     w1 * c[fm][fn][2]);
                atomicAdd(ob1 + cc + 1, w1 * c[fm][fn][3]);
            }
        }
    }
}

// ---------------------------------------------------------------------------
extern "C" void kernel_launch(void* const* d_in, const int* in_sizes, int n_in,
                              void* d_out, int out_size) {
    const float* x    = (const float*)d_in[0];
    const int*   eidx = (const int*)d_in[1];
    const float* ew   = (const float*)d_in[2];
    const float* gw   = (const float*)d_in[3];
    const float* uw   = (const float*)d_in[4];
    const float* dw   = (const float*)d_in[5];
    float*       out  = (float*)d_out;

    static int smem_set = 0;
    // Setting func attributes is idempotent and not a graph/stream op.
    cudaFuncSetAttribute(k_gateup, cudaFuncAttributeMaxDynamicSharedMemorySize, 2 * GU_BUF);
    cudaFuncSetAttribute(k_down,   cudaFuncAttributeMaxDynamicSharedMemorySize, 2 * DN_BUF);
    (void)smem_set;

    k_zero<<<1024, 256>>>(out);
    k_route<<<NP / 256, 256>>>(eidx);

    __nv_bfloat16 *xhi, *xlo, *ghi, *glo, *uhi, *ulo, *dhi, *dlo;
    cudaGetSymbolAddress((void**)&xhi, d_xhi);
    cudaGetSymbolAddress((void**)&xlo, d_xlo);
    cudaGetSymbolAddress((void**)&ghi, d_ghi);
    cudaGetSymbolAddress((void**)&glo, d_glo);
    cudaGetSymbolAddress((void**)&uhi, d_uhi);
    cudaGetSymbolAddress((void**)&ulo, d_ulo);
    cudaGetSymbolAddress((void**)&dhi, d_dhi);
    cudaGetSymbolAddress((void**)&dlo, d_dlo);

    k_split<<<2048, 256>>>(x,  xhi, xlo, (NT * HD) / 4);
    k_split<<<4096, 256>>>(gw, ghi, glo, (NE * ID * HD) / 4);
    k_split<<<4096, 256>>>(uw, uhi, ulo, (NE * ID * HD) / 4);
    k_split<<<4096, 256>>>(dw, dhi, dlo, (NE * HD * ID) / 4);

    // max sum of 128-row tiles = 8192/128 + (NE-1) = 71 -> 72
    dim3 g1(ID / 64, 72);
    k_gateup<<<g1, 256, 2 * GU_BUF>>>();

    dim3 g2(HD / 64, 72);
    k_down<<<g2, 256, 2 * DN_BUF>>>(ew, out);
}

// round 5
// speedup vs baseline: 3.5799x; 1.5267x over previous
#include <cuda_runtime.h>
#include <cuda_fp16.h>
#include <cstdint>

#define NT 4096      // tokens B*S
#define HD 1024      // hidden dim
#define ID 2048      // intermediate dim
#define NE 8         // experts
#define NP 8192      // NT * TOPK

#define SKP   40     // padded fp16 row stride in smem (32 k + 8 pad)
#define KCH   32     // K chunk

// ---------------- static device scratch (no cudaMalloc) ----------------
__device__ int d_cnt[NE];
__device__ int d_list[NE][NP];

__device__ __align__(16) __half d_xhi[(size_t)NT * HD];
__device__ __align__(16) __half d_xlo[(size_t)NT * HD];
__device__ __align__(16) __half d_g16[(size_t)NE * ID * HD];
__device__ __align__(16) __half d_u16[(size_t)NE * ID * HD];
__device__ __align__(16) __half d_d16[(size_t)NE * HD * ID];
__device__ __align__(16) __half d_hhi[(size_t)NP * ID];
__device__ __align__(16) __half d_hlo[(size_t)NP * ID];

// ---------------- PTX helpers ----------------
__device__ __forceinline__ uint32_t smem_u32(const void* p) {
    return (uint32_t)__cvta_generic_to_shared(p);
}
__device__ __forceinline__ void cp16(uint32_t dst, const void* src) {
    asm volatile("cp.async.cg.shared.global [%0], [%1], 16;\n" :: "r"(dst), "l"(src));
}
__device__ __forceinline__ void cp_commit() {
    asm volatile("cp.async.commit_group;\n");
}
template <int N>
__device__ __forceinline__ void cp_wait() {
    asm volatile("cp.async.wait_group %0;\n" :: "n"(N));
}
__device__ __forceinline__ void ldsm4(uint32_t r[4], uint32_t addr) {
    asm volatile("ldmatrix.sync.aligned.m8n8.x4.shared.b16 {%0,%1,%2,%3}, [%4];"
                 : "=r"(r[0]), "=r"(r[1]), "=r"(r[2]), "=r"(r[3]) : "r"(addr));
}
__device__ __forceinline__ void ldsm2(uint32_t r[2], uint32_t addr) {
    asm volatile("ldmatrix.sync.aligned.m8n8.x2.shared.b16 {%0,%1}, [%2];"
                 : "=r"(r[0]), "=r"(r[1]) : "r"(addr));
}
__device__ __forceinline__ void mma_f16(float c[4], const uint32_t a[4], const uint32_t b[2]) {
    asm volatile(
        "mma.sync.aligned.m16n8k16.row.col.f32.f16.f16.f32 "
        "{%0,%1,%2,%3}, {%4,%5,%6,%7}, {%8,%9}, {%0,%1,%2,%3};"
        : "+f"(c[0]), "+f"(c[1]), "+f"(c[2]), "+f"(c[3])
        : "r"(a[0]), "r"(a[1]), "r"(a[2]), "r"(a[3]), "r"(b[0]), "r"(b[1]));
}
__device__ __forceinline__ float silu_f(float v) { return v / (1.0f + __expf(-v)); }

__device__ __forceinline__ uint32_t pack_h2(float a, float b) {
    __half2 t;
    t.x = __float2half_rn(a);
    t.y = __float2half_rn(b);
    return *reinterpret_cast<uint32_t*>(&t);
}

// ---------------- kernel 0: zero out + counters ----------------
__global__ void k_zero(float* __restrict__ out) {
    const int stride = gridDim.x * blockDim.x;
    int i = blockIdx.x * blockDim.x + threadIdx.x;
    float4 z = make_float4(0.f, 0.f, 0.f, 0.f);
    float4* o4 = reinterpret_cast<float4*>(out);
    const int n4 = (NT * HD) / 4;
    for (int j = i; j < n4; j += stride) o4[j] = z;
    if (blockIdx.x == 0 && threadIdx.x < NE) d_cnt[threadIdx.x] = 0;
}

// ---------------- kernel 1: routing (expert_indices is int32) ----------------
__global__ void k_route(const int* __restrict__ eidx) {
    int p = blockIdx.x * blockDim.x + threadIdx.x;
    if (p < NP) {
        int e = eidx[p];
        if (e >= 0 && e < NE) {
            int pos = atomicAdd(&d_cnt[e], 1);
            d_list[e][pos] = p;
        }
    }
}

// ---------------- splits / converts ----------------
// x -> fp16 hi + lo (A operand needs 2-term accuracy)
__global__ void k_split2(const float* __restrict__ s,
                         __half* __restrict__ hi,
                         __half* __restrict__ lo, int n4) {
    int i = blockIdx.x * blockDim.x + threadIdx.x;
    int stride = gridDim.x * blockDim.x;
    const float4* s4 = (const float4*)s;
    uint2* h2 = (uint2*)hi;
    uint2* l2 = (uint2*)lo;
    for (int j = i; j < n4; j += stride) {
        float4 v = s4[j];
        __half h0 = __float2half_rn(v.x);
        __half h1 = __float2half_rn(v.y);
        __half h2v = __float2half_rn(v.z);
        __half h3 = __float2half_rn(v.w);
        uint2 H, L;
        __half2 t;
        t.x = h0; t.y = h1; H.x = *reinterpret_cast<uint32_t*>(&t);
        t.x = h2v; t.y = h3; H.y = *reinterpret_cast<uint32_t*>(&t);
        L.x = pack_h2(v.x - __half2float(h0), v.y - __half2float(h1));
        L.y = pack_h2(v.z - __half2float(h2v), v.w - __half2float(h3));
        h2[j] = H;
        l2[j] = L;
    }
}

// weights -> single fp16 plane (B operand: rounding error ~2^-12 is enough)
__global__ void k_cvt(const float* __restrict__ s, __half* __restrict__ d, int n4) {
    int i = blockIdx.x * blockDim.x + threadIdx.x;
    int stride = gridDim.x * blockDim.x;
    const float4* s4 = (const float4*)s;
    uint2* d2 = (uint2*)d;
    for (int j = i; j < n4; j += stride) {
        float4 v = s4[j];
        uint2 H;
        H.x = pack_h2(v.x, v.y);
        H.y = pack_h2(v.z, v.w);
        d2[j] = H;
    }
}

// Map global m-tile (128 rows) to (expert, local tile).
__device__ __forceinline__ bool map_tile(int g, int* pe, int* pmt) {
    int e = -1, mt = 0;
#pragma unroll
    for (int ee = 0; ee < NE; ee++) {
        int nt = (d_cnt[ee] + 127) >> 7;
        if (e < 0) {
            if (g < nt) { e = ee; mt = g; }
            else g -= nt;
        }
    }
    *pe = e; *pmt = mt;
    return e >= 0;
}

// ======================================================================
// Kernel 2: gate/up GEMM (M=128 rows, N=64 i-cols, K=HD) fp16 2-term MMA
// smem buffer (bytes): Ahi 0 (10240), Alo 10240 (10240), Bg 20480 (5120),
// Bu 25600 (5120); buffer stride 30720, double buffered.
// ======================================================================
#define GU_BUF 30720
#define GU_ALO 10240
#define GU_BG  20480
#define GU_BU  25600

__global__ void __launch_bounds__(256)
k_gateup() {
    int e, mt;
    if (!map_tile(blockIdx.y, &e, &mt)) return;
    const int n_e = d_cnt[e];
    const int m0  = mt * 128;
    const int i0  = blockIdx.x * 64;

    extern __shared__ __align__(16) unsigned char smem[];
    const uint32_t sbase = smem_u32(smem);

    const int tid  = threadIdx.x;
    const int wid  = tid >> 5;
    const int lane = tid & 31;

    // ---- staging pointers ----
    const int sr = tid >> 2;      // 0..63
    const int sc = tid & 3;       // 16B unit -> 8 fp16
    const __half *axh[2], *axl[2];
#pragma unroll
    for (int rp = 0; rp < 2; rp++) {
        int r = sr + rp * 64;
        int p = (m0 + r < n_e) ? d_list[e][m0 + r] : d_list[e][m0];
        size_t t = (size_t)(p >> 1);
        axh[rp] = d_xhi + t * HD + sc * 8;
        axl[rp] = d_xlo + t * HD + sc * 8;
    }
    const size_t wb = ((size_t)e * ID + i0 + sr) * HD + sc * 8;
    const __half* gp = d_g16 + wb;
    const __half* up = d_u16 + wb;

    const uint32_t adst = (uint32_t)(sr * (SKP * 2) + sc * 16);

    // ---- fragment addresses ----
    const int wm0 = (wid >> 1) * 32;
    const int wn0 = (wid & 1) * 32;
    const int lrA = lane & 15, lcA = lane >> 4;
    uint32_t aoff[2];
#pragma unroll
    for (int fm = 0; fm < 2; fm++)
        aoff[fm] = (uint32_t)(((wm0 + fm * 16 + lrA) * SKP + lcA * 8) * 2);
    const int lB = lane & 15;
    uint32_t boff[4];
#pragma unroll
    for (int fn = 0; fn < 4; fn++)
        boff[fn] = (uint32_t)(((wn0 + fn * 8 + (lB & 7)) * SKP + (lB >> 3) * 8) * 2);

    float cg[2][4][4] = {};
    float cu[2][4][4] = {};

    auto stage = [&](int kc, int b) {
        uint32_t B0 = sbase + (uint32_t)b * GU_BUF;
#pragma unroll
        for (int rp = 0; rp < 2; rp++) {
            uint32_t d = B0 + adst + (uint32_t)rp * 64 * (SKP * 2);
            cp16(d, axh[rp] + kc);
            cp16(d + GU_ALO, axl[rp] + kc);
        }
        uint32_t d = B0 + GU_BG + adst;
        cp16(d, gp + kc);
        cp16(d + (GU_BU - GU_BG), up + kc);
    };

    stage(0, 0);
    cp_commit();

    const int nch = HD / KCH;   // 32
    for (int ic = 0; ic < nch; ic++) {
        if (ic + 1 < nch) {
            stage((ic + 1) * KCH, (ic + 1) & 1);
            cp_commit();
            cp_wait<1>();
        } else {
            cp_wait<0>();
        }
        __syncthreads();
        const uint32_t B0 = sbase + (uint32_t)(ic & 1) * GU_BUF;
#pragma unroll
        for (int ks = 0; ks < KCH; ks += 16) {
            uint32_t ah[2][4], al[2][4];
#pragma unroll
            for (int fm = 0; fm < 2; fm++) {
                ldsm4(ah[fm], B0 + aoff[fm] + ks * 2);
                ldsm4(al[fm], B0 + GU_ALO + aoff[fm] + ks * 2);
            }
            uint32_t bg[4][2], bu[4][2];
#pragma unroll
            for (int fn = 0; fn < 4; fn++) {
                ldsm2(bg[fn], B0 + GU_BG + boff[fn] + ks * 2);
                ldsm2(bu[fn], B0 + GU_BU + boff[fn] + ks * 2);
            }
#pragma unroll
            for (int fm = 0; fm < 2; fm++)
#pragma unroll
                for (int fn = 0; fn < 4; fn++) {
                    mma_f16(cg[fm][fn], ah[fm], bg[fn]);
                    mma_f16(cu[fm][fn], ah[fm], bu[fn]);
                    mma_f16(cg[fm][fn], al[fm], bg[fn]);
                    mma_f16(cu[fm][fn], al[fm], bu[fn]);
                }
        }
        __syncthreads();
    }

    // ---- epilogue: h = silu(gate)*up, split to fp16 hi/lo planes ----
    const int g4  = lane >> 2;
    const int tig = lane & 3;
#pragma unroll
    for (int fm = 0; fm < 2; fm++) {
#pragma unroll
        for (int fn = 0; fn < 4; fn++) {
            int cc = wn0 + fn * 8 + tig * 2;
            int r0 = wm0 + fm * 16 + g4;
            int r1 = r0 + 8;
            float v00 = silu_f(cg[fm][fn][0]) * cu[fm][fn][0];
            float v01 = silu_f(cg[fm][fn][1]) * cu[fm][fn][1];
            float v10 = silu_f(cg[fm][fn][2]) * cu[fm][fn][2];
            float v11 = silu_f(cg[fm][fn][3]) * cu[fm][fn][3];
            if (m0 + r0 < n_e) {
                int p = d_list[e][m0 + r0];
                size_t idx = (size_t)p * ID + i0 + cc;
                __half h0 = __float2half_rn(v00);
                __half h1 = __float2half_rn(v01);
                __half2 H; H.x = h0; H.y = h1;
                *reinterpret_cast<uint32_t*>(&d_hhi[idx]) = *reinterpret_cast<uint32_t*>(&H);
                *reinterpret_cast<uint32_t*>(&d_hlo[idx]) =
                    pack_h2(v00 - __half2float(h0), v01 - __half2float(h1));
            }
            if (m0 + r1 < n_e) {
                int p = d_list[e][m0 + r1];
                size_t idx = (size_t)p * ID + i0 + cc;
                __half h0 = __float2half_rn(v10);
                __half h1 = __float2half_rn(v11);
                __half2 H; H.x = h0; H.y = h1;
                *reinterpret_cast<uint32_t*>(&d_hhi[idx]) = *reinterpret_cast<uint32_t*>(&H);
                *reinterpret_cast<uint32_t*>(&d_hlo[idx]) =
                    pack_h2(v10 - __half2float(h0), v11 - __half2float(h1));
            }
        }
    }
}

// ======================================================================
// Kernel 3: down GEMM (M=128 rows, N=64 h-cols, K=ID) fp16 2-term MMA
// buffer: Ahi 0 (10240), Alo 10240 (10240), B 20480 (5120); stride 25600 x2.
// ======================================================================
#define DN_BUF 25600
#define DN_ALO 10240
#define DN_B   20480

__global__ void __launch_bounds__(256)
k_down(const float* __restrict__ ew, float* __restrict__ out) {
    int e, mt;
    if (!map_tile(blockIdx.y, &e, &mt)) return;
    const int n_e = d_cnt[e];
    const int m0  = mt * 128;
    const int n0  = blockIdx.x * 64;

    extern __shared__ __align__(16) unsigned char smem[];
    const uint32_t sbase = smem_u32(smem);

    const int tid  = threadIdx.x;
    const int wid  = tid >> 5;
    const int lane = tid & 31;

    const int sr = tid >> 2;
    const int sc = tid & 3;
    const __half *ahp[2], *alp[2];
#pragma unroll
    for (int rp = 0; rp < 2; rp++) {
        int r = sr + rp * 64;
        int p = (m0 + r < n_e) ? d_list[e][m0 + r] : d_list[e][m0];
        ahp[rp] = d_hhi + (size_t)p * ID + sc * 8;
        alp[rp] = d_hlo + (size_t)p * ID + sc * 8;
    }
    const size_t wb = ((size_t)e * HD + n0 + sr) * ID + sc * 8;
    const __half* bp = d_d16 + wb;

    const uint32_t adst = (uint32_t)(sr * (SKP * 2) + sc * 16);

    const int wm0 = (wid >> 1) * 32;
    const int wn0 = (wid & 1) * 32;
    const int lrA = lane & 15, lcA = lane >> 4;
    uint32_t aoff[2];
#pragma unroll
    for (int fm = 0; fm < 2; fm++)
        aoff[fm] = (uint32_t)(((wm0 + fm * 16 + lrA) * SKP + lcA * 8) * 2);
    const int lB = lane & 15;
    uint32_t boff[4];
#pragma unroll
    for (int fn = 0; fn < 4; fn++)
        boff[fn] = (uint32_t)(((wn0 + fn * 8 + (lB & 7)) * SKP + (lB >> 3) * 8) * 2);

    float c[2][4][4] = {};

    auto stage = [&](int kc, int b) {
        uint32_t B0 = sbase + (uint32_t)b * DN_BUF;
#pragma unroll
        for (int rp = 0; rp < 2; rp++) {
            uint32_t d = B0 + adst + (uint32_t)rp * 64 * (SKP * 2);
            cp16(d, ahp[rp] + kc);
            cp16(d + DN_ALO, alp[rp] + kc);
        }
        cp16(sbase + (uint32_t)b * DN_BUF + DN_B + adst, bp + kc);
    };

    stage(0, 0);
    cp_commit();

    const int nch = ID / KCH;   // 64
    for (int ic = 0; ic < nch; ic++) {
        if (ic + 1 < nch) {
            stage((ic + 1) * KCH, (ic + 1) & 1);
            cp_commit();
            cp_wait<1>();
        } else {
            cp_wait<0>();
        }
        __syncthreads();
        const uint32_t B0 = sbase + (uint32_t)(ic & 1) * DN_BUF;
#pragma unroll
        for (int ks = 0; ks < KCH; ks += 16) {
            uint32_t ah[2][4], al[2][4];
#pragma unroll
            for (int fm = 0; fm < 2; fm++) {
                ldsm4(ah[fm], B0 + aoff[fm] + ks * 2);
                ldsm4(al[fm], B0 + DN_ALO + aoff[fm] + ks * 2);
            }
            uint32_t bf[4][2];
#pragma unroll
            for (int fn = 0; fn < 4; fn++)
                ldsm2(bf[fn], B0 + DN_B + boff[fn] + ks * 2);
#pragma unroll
            for (int fm = 0; fm < 2; fm++)
#pragma unroll
                for (int fn = 0; fn < 4; fn++) {
                    mma_f16(c[fm][fn], ah[fm], bf[fn]);
                    mma_f16(c[fm][fn], al[fm], bf[fn]);
                }
        }
        __syncthreads();
    }

    // ---- epilogue: weighted atomic scatter ----
    const int g4  = lane >> 2;
    const int tig = lane & 3;
#pragma unroll
    for (int fm = 0; fm < 2; fm++) {
        int r0 = wm0 + fm * 16 + g4;
        int r1 = r0 + 8;
        bool v0 = (m0 + r0 < n_e), v1 = (m0 + r1 < n_e);
        int p0 = v0 ? d_list[e][m0 + r0] : 0;
        int p1 = v1 ? d_list[e][m0 + r1] : 0;
        float w0 = v0 ? __ldg(&ew[p0]) : 0.0f;
        float w1 = v1 ? __ldg(&ew[p1]) : 0.0f;
        float* ob0 = out + (size_t)(p0 >> 1) * HD + n0;
        float* ob1 = out + (size_t)(p1 >> 1) * HD + n0;
#pragma unroll
        for (int fn = 0; fn < 4; fn++) {
            int cc = wn0 + fn * 8 + tig * 2;
            if (v0) {
                atomicAdd(ob0 + cc,     w0 * c[fm][fn][0]);
                atomicAdd(ob0 + cc + 1, w0 * c[fm][fn][1]);
            }
            if (v1) {
                atomicAdd(ob1 + cc,     w1 * c[fm][fn][2]);
                atomicAdd(ob1 + cc + 1, w1 * c[fm][fn][3]);
            }
        }
    }
}

// ---------------------------------------------------------------------------
extern "C" void kernel_launch(void* const* d_in, const int* in_sizes, int n_in,
                              void* d_out, int out_size) {
    const float* x    = (const float*)d_in[0];
    const int*   eidx = (const int*)d_in[1];
    const float* ew   = (const float*)d_in[2];
    const float* gw   = (const float*)d_in[3];
    const float* uw   = (const float*)d_in[4];
    const float* dw   = (const float*)d_in[5];
    float*       out  = (float*)d_out;

    cudaFuncSetAttribute(k_gateup, cudaFuncAttributeMaxDynamicSharedMemorySize, 2 * GU_BUF);
    cudaFuncSetAttribute(k_down,   cudaFuncAttributeMaxDynamicSharedMemorySize, 2 * DN_BUF);

    k_zero<<<1024, 256>>>(out);
    k_route<<<NP / 256, 256>>>(eidx);

    __half *xhi, *xlo, *g16, *u16, *d16;
    cudaGetSymbolAddress((void**)&xhi, d_xhi);
    cudaGetSymbolAddress((void**)&xlo, d_xlo);
    cudaGetSymbolAddress((void**)&g16, d_g16);
    cudaGetSymbolAddress((void**)&u16, d_u16);
    cudaGetSymbolAddress((void**)&d16, d_d16);

    k_split2<<<2048, 256>>>(x, xhi, xlo, (NT * HD) / 4);
    k_cvt<<<4096, 256>>>(gw, g16, (NE * ID * HD) / 4);
    k_cvt<<<4096, 256>>>(uw, u16, (NE * ID * HD) / 4);
    k_cvt<<<4096, 256>>>(dw, d16, (NE * HD * ID) / 4);

    // max sum of 128-row tiles = 8192/128 + (NE-1) = 71 -> 72
    dim3 g1(ID / 64, 72);
    k_gateup<<<g1, 256, 2 * GU_BUF>>>();

    dim3 g2(HD / 64, 72);
    k_down<<<g2, 256, 2 * DN_BUF>>>(ew, out);
}

// round 6
// speedup vs baseline: 5.6255x; 1.5714x over previous
#include <cuda_runtime.h>
#include <cuda_fp16.h>
#include <cstdint>

#define NT 4096      // tokens B*S
#define HD 1024      // hidden dim
#define ID 2048      // intermediate dim
#define NE 8         // experts
#define NP 8192      // NT * TOPK

#define SKP   40     // padded fp16 row stride in smem (32 k + 8 pad)
#define KCH   32     // K chunk

// ---------------- static device scratch (no cudaMalloc) ----------------
__device__ int d_cnt[NE];
__device__ int d_list[NE][NP];

__device__ __align__(16) __half d_x16[(size_t)NT * HD];
__device__ __align__(16) __half d_g16[(size_t)NE * ID * HD];
__device__ __align__(16) __half d_u16[(size_t)NE * ID * HD];
__device__ __align__(16) __half d_d16[(size_t)NE * HD * ID];
__device__ __align__(16) __half d_h16[(size_t)NP * ID];

// ---------------- PTX helpers ----------------
__device__ __forceinline__ uint32_t smem_u32(const void* p) {
    return (uint32_t)__cvta_generic_to_shared(p);
}
__device__ __forceinline__ void cp16(uint32_t dst, const void* src) {
    asm volatile("cp.async.cg.shared.global [%0], [%1], 16;\n" :: "r"(dst), "l"(src));
}
__device__ __forceinline__ void cp_commit() {
    asm volatile("cp.async.commit_group;\n");
}
template <int N>
__device__ __forceinline__ void cp_wait() {
    asm volatile("cp.async.wait_group %0;\n" :: "n"(N));
}
__device__ __forceinline__ void ldsm4(uint32_t r[4], uint32_t addr) {
    asm volatile("ldmatrix.sync.aligned.m8n8.x4.shared.b16 {%0,%1,%2,%3}, [%4];"
                 : "=r"(r[0]), "=r"(r[1]), "=r"(r[2]), "=r"(r[3]) : "r"(addr));
}
__device__ __forceinline__ void ldsm2(uint32_t r[2], uint32_t addr) {
    asm volatile("ldmatrix.sync.aligned.m8n8.x2.shared.b16 {%0,%1}, [%2];"
                 : "=r"(r[0]), "=r"(r[1]) : "r"(addr));
}
__device__ __forceinline__ void mma_f16(float c[4], const uint32_t a[4], const uint32_t b[2]) {
    asm volatile(
        "mma.sync.aligned.m16n8k16.row.col.f32.f16.f16.f32 "
        "{%0,%1,%2,%3}, {%4,%5,%6,%7}, {%8,%9}, {%0,%1,%2,%3};"
        : "+f"(c[0]), "+f"(c[1]), "+f"(c[2]), "+f"(c[3])
        : "r"(a[0]), "r"(a[1]), "r"(a[2]), "r"(a[3]), "r"(b[0]), "r"(b[1]));
}
__device__ __forceinline__ float silu_f(float v) { return v / (1.0f + __expf(-v)); }

__device__ __forceinline__ uint32_t pack_h2(float a, float b) {
    __half2 t;
    t.x = __float2half_rn(a);
    t.y = __float2half_rn(b);
    return *reinterpret_cast<uint32_t*>(&t);
}

// ---------------- kernel 0: zero out + counters ----------------
__global__ void k_zero(float* __restrict__ out) {
    const int stride = gridDim.x * blockDim.x;
    int i = blockIdx.x * blockDim.x + threadIdx.x;
    float4 z = make_float4(0.f, 0.f, 0.f, 0.f);
    float4* o4 = reinterpret_cast<float4*>(out);
    const int n4 = (NT * HD) / 4;
    for (int j = i; j < n4; j += stride) o4[j] = z;
    if (blockIdx.x == 0 && threadIdx.x < NE) d_cnt[threadIdx.x] = 0;
}

// ---------------- kernel 1: routing (expert_indices is int32) ----------------
__global__ void k_route(const int* __restrict__ eidx) {
    int p = blockIdx.x * blockDim.x + threadIdx.x;
    if (p < NP) {
        int e = eidx[p];
        if (e >= 0 && e < NE) {
            int pos = atomicAdd(&d_cnt[e], 1);
            d_list[e][pos] = p;
        }
    }
}

// ---------------- fp32 -> fp16 convert ----------------
__global__ void k_cvt(const float* __restrict__ s, __half* __restrict__ d, int n4) {
    int i = blockIdx.x * blockDim.x + threadIdx.x;
    int stride = gridDim.x * blockDim.x;
    const float4* s4 = (const float4*)s;
    uint2* d2 = (uint2*)d;
    for (int j = i; j < n4; j += stride) {
        float4 v = s4[j];
        uint2 H;
        H.x = pack_h2(v.x, v.y);
        H.y = pack_h2(v.z, v.w);
        d2[j] = H;
    }
}

// Map global m-tile (128 rows) to (expert, local tile).
__device__ __forceinline__ bool map_tile(int g, int* pe, int* pmt) {
    int e = -1, mt = 0;
#pragma unroll
    for (int ee = 0; ee < NE; ee++) {
        int nt = (d_cnt[ee] + 127) >> 7;
        if (e < 0) {
            if (g < nt) { e = ee; mt = g; }
            else g -= nt;
        }
    }
    *pe = e; *pmt = mt;
    return e >= 0;
}

// ======================================================================
// Kernel 2: gate/up GEMM (M=128 rows, N=64 i-cols, K=HD) fp16 MMA
// smem buffer (bytes): A 0 (10240), Bg 10240 (5120), Bu 15360 (5120);
// buffer stride 20480, double buffered.
// ======================================================================
#define GU_BUF 20480
#define GU_BG  10240
#define GU_BU  15360

__global__ void __launch_bounds__(256)
k_gateup() {
    int e, mt;
    if (!map_tile(blockIdx.y, &e, &mt)) return;
    const int n_e = d_cnt[e];
    const int m0  = mt * 128;
    const int i0  = blockIdx.x * 64;

    extern __shared__ __align__(16) unsigned char smem[];
    const uint32_t sbase = smem_u32(smem);

    const int tid  = threadIdx.x;
    const int wid  = tid >> 5;
    const int lane = tid & 31;

    // ---- staging pointers ----
    const int sr = tid >> 2;      // 0..63
    const int sc = tid & 3;       // 16B unit -> 8 fp16
    const __half* axp[2];
#pragma unroll
    for (int rp = 0; rp < 2; rp++) {
        int r = sr + rp * 64;
        int p = (m0 + r < n_e) ? d_list[e][m0 + r] : d_list[e][m0];
        axp[rp] = d_x16 + (size_t)(p >> 1) * HD + sc * 8;
    }
    const size_t wb = ((size_t)e * ID + i0 + sr) * HD + sc * 8;
    const __half* gp = d_g16 + wb;
    const __half* up = d_u16 + wb;

    const uint32_t adst = (uint32_t)(sr * (SKP * 2) + sc * 16);

    // ---- fragment addresses ----
    const int wm0 = (wid >> 1) * 32;
    const int wn0 = (wid & 1) * 32;
    const int lrA = lane & 15, lcA = lane >> 4;
    uint32_t aoff[2];
#pragma unroll
    for (int fm = 0; fm < 2; fm++)
        aoff[fm] = (uint32_t)(((wm0 + fm * 16 + lrA) * SKP + lcA * 8) * 2);
    const int lB = lane & 15;
    uint32_t boff[4];
#pragma unroll
    for (int fn = 0; fn < 4; fn++)
        boff[fn] = (uint32_t)(((wn0 + fn * 8 + (lB & 7)) * SKP + (lB >> 3) * 8) * 2);

    float cg[2][4][4] = {};
    float cu[2][4][4] = {};

    auto stage = [&](int kc, int b) {
        uint32_t B0 = sbase + (uint32_t)b * GU_BUF;
#pragma unroll
        for (int rp = 0; rp < 2; rp++)
            cp16(B0 + adst + (uint32_t)rp * 64 * (SKP * 2), axp[rp] + kc);
        uint32_t d = B0 + GU_BG + adst;
        cp16(d, gp + kc);
        cp16(d + (GU_BU - GU_BG), up + kc);
    };

    stage(0, 0);
    cp_commit();

    const int nch = HD / KCH;   // 32
    for (int ic = 0; ic < nch; ic++) {
        if (ic + 1 < nch) {
            stage((ic + 1) * KCH, (ic + 1) & 1);
            cp_commit();
            cp_wait<1>();
        } else {
            cp_wait<0>();
        }
        __syncthreads();
        const uint32_t B0 = sbase + (uint32_t)(ic & 1) * GU_BUF;
#pragma unroll
        for (int ks = 0; ks < KCH; ks += 16) {
            uint32_t a[2][4];
#pragma unroll
            for (int fm = 0; fm < 2; fm++)
                ldsm4(a[fm], B0 + aoff[fm] + ks * 2);
            uint32_t bg[4][2], bu[4][2];
#pragma unroll
            for (int fn = 0; fn < 4; fn++) {
                ldsm2(bg[fn], B0 + GU_BG + boff[fn] + ks * 2);
                ldsm2(bu[fn], B0 + GU_BU + boff[fn] + ks * 2);
            }
#pragma unroll
            for (int fm = 0; fm < 2; fm++)
#pragma unroll
                for (int fn = 0; fn < 4; fn++) {
                    mma_f16(cg[fm][fn], a[fm], bg[fn]);
                    mma_f16(cu[fm][fn], a[fm], bu[fn]);
                }
        }
        __syncthreads();
    }

    // ---- epilogue: h = silu(gate)*up -> fp16 ----
    const int g4  = lane >> 2;
    const int tig = lane & 3;
#pragma unroll
    for (int fm = 0; fm < 2; fm++) {
#pragma unroll
        for (int fn = 0; fn < 4; fn++) {
            int cc = wn0 + fn * 8 + tig * 2;
            int r0 = wm0 + fm * 16 + g4;
            int r1 = r0 + 8;
            float v00 = silu_f(cg[fm][fn][0]) * cu[fm][fn][0];
            float v01 = silu_f(cg[fm][fn][1]) * cu[fm][fn][1];
            float v10 = silu_f(cg[fm][fn][2]) * cu[fm][fn][2];
            float v11 = silu_f(cg[fm][fn][3]) * cu[fm][fn][3];
            if (m0 + r0 < n_e) {
                int p = d_list[e][m0 + r0];
                *reinterpret_cast<uint32_t*>(&d_h16[(size_t)p * ID + i0 + cc]) =
                    pack_h2(v00, v01);
            }
            if (m0 + r1 < n_e) {
                int p = d_list[e][m0 + r1];
                *reinterpret_cast<uint32_t*>(&d_h16[(size_t)p * ID + i0 + cc]) =
                    pack_h2(v10, v11);
            }
        }
    }
}

// ======================================================================
// Kernel 3: down GEMM (M=128 rows, N=64 h-cols, K=ID) fp16 MMA
// buffer: A 0 (10240), B 10240 (5120); stride 15360, double buffered.
// ======================================================================
#define DN_BUF 15360
#define DN_B   10240

__global__ void __launch_bounds__(256)
k_down(const float* __restrict__ ew, float* __restrict__ out) {
    int e, mt;
    if (!map_tile(blockIdx.y, &e, &mt)) return;
    const int n_e = d_cnt[e];
    const int m0  = mt * 128;
    const int n0  = blockIdx.x * 64;

    extern __shared__ __align__(16) unsigned char smem[];
    const uint32_t sbase = smem_u32(smem);

    const int tid  = threadIdx.x;
    const int wid  = tid >> 5;
    const int lane = tid & 31;

    const int sr = tid >> 2;
    const int sc = tid & 3;
    const __half* ahp[2];
#pragma unroll
    for (int rp = 0; rp < 2; rp++) {
        int r = sr + rp * 64;
        int p = (m0 + r < n_e) ? d_list[e][m0 + r] : d_list[e][m0];
        ahp[rp] = d_h16 + (size_t)p * ID + sc * 8;
    }
    const size_t wb = ((size_t)e * HD + n0 + sr) * ID + sc * 8;
    const __half* bp = d_d16 + wb;

    const uint32_t adst = (uint32_t)(sr * (SKP * 2) + sc * 16);

    const int wm0 = (wid >> 1) * 32;
    const int wn0 = (wid & 1) * 32;
    const int lrA = lane & 15, lcA = lane >> 4;
    uint32_t aoff[2];
#pragma unroll
    for (int fm = 0; fm < 2; fm++)
        aoff[fm] = (uint32_t)(((wm0 + fm * 16 + lrA) * SKP + lcA * 8) * 2);
    const int lB = lane & 15;
    uint32_t boff[4];
#pragma unroll
    for (int fn = 0; fn < 4; fn++)
        boff[fn] = (uint32_t)(((wn0 + fn * 8 + (lB & 7)) * SKP + (lB >> 3) * 8) * 2);

    float c[2][4][4] = {};

    auto stage = [&](int kc, int b) {
        uint32_t B0 = sbase + (uint32_t)b * DN_BUF;
#pragma unroll
        for (int rp = 0; rp < 2; rp++)
            cp16(B0 + adst + (uint32_t)rp * 64 * (SKP * 2), ahp[rp] + kc);
        cp16(B0 + DN_B + adst, bp + kc);
    };

    stage(0, 0);
    cp_commit();

    const int nch = ID / KCH;   // 64
    for (int ic = 0; ic < nch; ic++) {
        if (ic + 1 < nch) {
            stage((ic + 1) * KCH, (ic + 1) & 1);
            cp_commit();
            cp_wait<1>();
        } else {
            cp_wait<0>();
        }
        __syncthreads();
        const uint32_t B0 = sbase + (uint32_t)(ic & 1) * DN_BUF;
#pragma unroll
        for (int ks = 0; ks < KCH; ks += 16) {
            uint32_t a[2][4];
#pragma unroll
            for (int fm = 0; fm < 2; fm++)
                ldsm4(a[fm], B0 + aoff[fm] + ks * 2);
            uint32_t bf[4][2];
#pragma unroll
            for (int fn = 0; fn < 4; fn++)
                ldsm2(bf[fn], B0 + DN_B + boff[fn] + ks * 2);
#pragma unroll
            for (int fm = 0; fm < 2; fm++)
#pragma unroll
                for (int fn = 0; fn < 4; fn++)
                    mma_f16(c[fm][fn], a[fm], bf[fn]);
        }
        __syncthreads();
    }

    // ---- epilogue: weighted atomic scatter ----
    const int g4  = lane >> 2;
    const int tig = lane & 3;
#pragma unroll
    for (int fm = 0; fm < 2; fm++) {
        int r0 = wm0 + fm * 16 + g4;
        int r1 = r0 + 8;
        bool v0 = (m0 + r0 < n_e), v1 = (m0 + r1 < n_e);
        int p0 = v0 ? d_list[e][m0 + r0] : 0;
        int p1 = v1 ? d_list[e][m0 + r1] : 0;
        float w0 = v0 ? __ldg(&ew[p0]) : 0.0f;
        float w1 = v1 ? __ldg(&ew[p1]) : 0.0f;
        float* ob0 = out + (size_t)(p0 >> 1) * HD + n0;
        float* ob1 = out + (size_t)(p1 >> 1) * HD + n0;
#pragma unroll
        for (int fn = 0; fn < 4; fn++) {
            int cc = wn0 + fn * 8 + tig * 2;
            if (v0) {
                atomicAdd(ob0 + cc,     w0 * c[fm][fn][0]);
                atomicAdd(ob0 + cc + 1, w0 * c[fm][fn][1]);
            }
            if (v1) {
                atomicAdd(ob1 + cc,     w1 * c[fm][fn][2]);
                atomicAdd(ob1 + cc + 1, w1 * c[fm][fn][3]);
            }
        }
    }
}

// ---------------------------------------------------------------------------
extern "C" void kernel_launch(void* const* d_in, const int* in_sizes, int n_in,
                              void* d_out, int out_size) {
    const float* x    = (const float*)d_in[0];
    const int*   eidx = (const int*)d_in[1];
    const float* ew   = (const float*)d_in[2];
    const float* gw   = (const float*)d_in[3];
    const float* uw   = (const float*)d_in[4];
    const float* dw   = (const float*)d_in[5];
    float*       out  = (float*)d_out;

    cudaFuncSetAttribute(k_gateup, cudaFuncAttributeMaxDynamicSharedMemorySize, 2 * GU_BUF);
    cudaFuncSetAttribute(k_down,   cudaFuncAttributeMaxDynamicSharedMemorySize, 2 * DN_BUF);

    k_zero<<<1024, 256>>>(out);
    k_route<<<NP / 256, 256>>>(eidx);

    __half *x16, *g16, *u16, *d16;
    cudaGetSymbolAddress((void**)&x16, d_x16);
    cudaGetSymbolAddress((void**)&g16, d_g16);
    cudaGetSymbolAddress((void**)&u16, d_u16);
    cudaGetSymbolAddress((void**)&d16, d_d16);

    k_cvt<<<2048, 256>>>(x,  x16, (NT * HD) / 4);
    k_cvt<<<4096, 256>>>(gw, g16, (NE * ID * HD) / 4);
    k_cvt<<<4096, 256>>>(uw, u16, (NE * ID * HD) / 4);
    k_cvt<<<4096, 256>>>(dw, d16, (NE * HD * ID) / 4);

    // max sum of 128-row tiles = 8192/128 + (NE-1) = 71 -> 72
    dim3 g1(ID / 64, 72);
    k_gateup<<<g1, 256, 2 * GU_BUF>>>();

    dim3 g2(HD / 64, 72);
    k_down<<<g2, 256, 2 * DN_BUF>>>(ew, out);
}